// round 1
// baseline (speedup 1.0000x reference)
#include <cuda_runtime.h>
#include <math.h>

#define NN 100000
#define EE 3200000
#define DD 64
constexpr float EPSF = 0.01f;

// ---------------- scratch (device globals; no allocation allowed) ----------------
__device__ __align__(16) float g_x [NN * DD];   // node state h
__device__ __align__(16) float g_v [NN * DD];   // velocity
__device__ __align__(16) float g_lx[NN * DD];   // x @ lin_w + lin_b
__device__ __align__(16) float g_dd[NN * DD];   // relu(x @ diss_w + diss_b)
__device__ __align__(16) float g_ff[NN * DD];   // x @ forc_w + forc_b
__device__ __align__(16) float g_a  [NN];
__device__ __align__(16) float g_b  [NN];       // x@wb + rb
__device__ __align__(16) float g_deg[NN];
__device__ __align__(16) float2 g_ad[NN];       // (a, dinv)
__device__ __align__(16) int g_cnt [NN];
__device__ __align__(16) int g_ptr [NN + 1];
__device__ __align__(16) int g_fill[NN];
__device__ __align__(16) int g_src [EE];        // CSR-by-col: source node per slot

// ---------------- CSR build ----------------
__global__ void zero_cnt_kernel() {
    int i = blockIdx.x * blockDim.x + threadIdx.x;
    if (i < NN) g_cnt[i] = 0;
}

__global__ void count_kernel(const int* __restrict__ ei) {
    int e = blockIdx.x * blockDim.x + threadIdx.x;
    if (e >= EE) return;
    atomicAdd(&g_cnt[ei[EE + e]], 1);
}

__global__ void scan_kernel() {
    __shared__ int sm[1024];
    int tid = threadIdx.x;
    const int CH = (NN + 1023) / 1024;
    int lo = tid * CH;
    int hi = lo + CH; if (hi > NN) hi = NN;
    int s = 0;
    for (int i = lo; i < hi; ++i) s += g_cnt[i];
    sm[tid] = s;
    __syncthreads();
    for (int off = 1; off < 1024; off <<= 1) {
        int v = (tid >= off) ? sm[tid - off] : 0;
        __syncthreads();
        sm[tid] += v;
        __syncthreads();
    }
    int run = sm[tid] - s;
    for (int i = lo; i < hi; ++i) {
        g_ptr[i] = run; g_fill[i] = run;
        run += g_cnt[i];
    }
    if (tid == 1023) g_ptr[NN] = sm[1023];
}

__global__ void scatter_kernel(const int* __restrict__ ei) {
    int e = blockIdx.x * blockDim.x + threadIdx.x;
    if (e >= EE) return;
    int r = ei[e], c = ei[EE + e];
    int slot = atomicAdd(&g_fill[c], 1);
    g_src[slot] = r;
}

// ---------------- shared helpers ----------------
__device__ __forceinline__ void load_xtile(const float* __restrict__ X, float* Xs,
                                           int node0, int nrows, int tid) {
    // Xs[k][m], pitch 68 floats, 64x64 tile transposed
    for (int i = tid; i < 1024; i += 256) {
        int m = i >> 4, q = i & 15;
        float4 v = make_float4(0.f, 0.f, 0.f, 0.f);
        int node = node0 + m;
        if (node < nrows) v = reinterpret_cast<const float4*>(X)[node * 16 + q];
        int k = q * 4;
        Xs[(k + 0) * 68 + m] = v.x;
        Xs[(k + 1) * 68 + m] = v.y;
        Xs[(k + 2) * 68 + m] = v.z;
        Xs[(k + 3) * 68 + m] = v.w;
    }
}

__device__ __forceinline__ float gelu_tanh(float x) {
    float x3 = x * x * x;
    float t = tanhf(0.7978845608028654f * (x + 0.044715f * x3));
    return 0.5f * x * (1.0f + t);
}

// ---------------- generic GEMM: Y[m][0..BN) = X[m] @ W + bias ----------------
template <int BN>
__global__ void gemm_kernel(const float* __restrict__ X, const float* __restrict__ W,
                            const float* __restrict__ bias, float* __restrict__ Y,
                            int nrows) {
    __shared__ float Ws[64 * BN];
    __shared__ float Xs[64 * 68];
    int tid = threadIdx.x;
    for (int i = tid; i < 64 * BN / 4; i += 256)
        reinterpret_cast<float4*>(Ws)[i] = reinterpret_cast<const float4*>(W)[i];
    int node0 = blockIdx.x * 64;
    load_xtile(X, Xs, node0, nrows, tid);
    __syncthreads();

    constexpr int NT = BN / 16;
    int tm = tid & 15, tn = tid >> 4;
    int m0 = tm * 4;
    float acc[4][NT];
#pragma unroll
    for (int i = 0; i < 4; ++i)
#pragma unroll
        for (int j = 0; j < NT; ++j) acc[i][j] = 0.f;

#pragma unroll 4
    for (int k = 0; k < 64; ++k) {
        float4 xv = *reinterpret_cast<const float4*>(Xs + k * 68 + m0);
        float xr[4] = {xv.x, xv.y, xv.z, xv.w};
        float wr[NT];
#pragma unroll
        for (int j = 0; j < NT; ++j) wr[j] = Ws[k * BN + tn * NT + j];
#pragma unroll
        for (int i = 0; i < 4; ++i)
#pragma unroll
            for (int j = 0; j < NT; ++j) acc[i][j] = fmaf(xr[i], wr[j], acc[i][j]);
    }
    float br[NT];
#pragma unroll
    for (int j = 0; j < NT; ++j) br[j] = bias[tn * NT + j];
#pragma unroll
    for (int i = 0; i < 4; ++i) {
        int m = node0 + m0 + i;
        if (m < nrows) {
#pragma unroll
            for (int j = 0; j < NT; ++j) Y[m * BN + tn * NT + j] = acc[i][j] + br[j];
        }
    }
}

// ---------------- k1: lx / relu(diss) / forc in one pass ----------------
__global__ void k1_kernel(const float* __restrict__ Wl, const float* __restrict__ bl,
                          const float* __restrict__ Wd, const float* __restrict__ bd,
                          const float* __restrict__ Wf, const float* __restrict__ bf) {
    extern __shared__ float sm[];
    float* Ws = sm;              // 64 x 192 (cols: 0-63 lin, 64-127 diss, 128-191 forc)
    float* Xs = sm + 64 * 192;   // 64 x 68
    int tid = threadIdx.x;
    for (int i = tid; i < 3072; i += 256) {  // 3072 float4 = 12288 floats
        int k = i / 48, q = i % 48;
        const float* src = (q < 16) ? Wl : (q < 32) ? Wd : Wf;
        int qq = q & 15;
        reinterpret_cast<float4*>(Ws + k * 192)[q] =
            reinterpret_cast<const float4*>(src + k * 64)[qq];
    }
    int node0 = blockIdx.x * 64;
    load_xtile(g_x, Xs, node0, NN, tid);
    __syncthreads();

    int tm = tid & 15, tn = tid >> 4;
    int m0 = tm * 4;
    float acc[4][3][4];
#pragma unroll
    for (int i = 0; i < 4; ++i)
#pragma unroll
        for (int s = 0; s < 3; ++s)
#pragma unroll
            for (int j = 0; j < 4; ++j) acc[i][s][j] = 0.f;

#pragma unroll 4
    for (int k = 0; k < 64; ++k) {
        float4 xv = *reinterpret_cast<const float4*>(Xs + k * 68 + m0);
        float xr[4] = {xv.x, xv.y, xv.z, xv.w};
#pragma unroll
        for (int s = 0; s < 3; ++s) {
            float4 wv = *reinterpret_cast<const float4*>(Ws + k * 192 + s * 64 + tn * 4);
            float wr[4] = {wv.x, wv.y, wv.z, wv.w};
#pragma unroll
            for (int i = 0; i < 4; ++i)
#pragma unroll
                for (int j = 0; j < 4; ++j)
                    acc[i][s][j] = fmaf(xr[i], wr[j], acc[i][s][j]);
        }
    }
    float4 b_l = *reinterpret_cast<const float4*>(bl + tn * 4);
    float4 b_d = *reinterpret_cast<const float4*>(bd + tn * 4);
    float4 b_f = *reinterpret_cast<const float4*>(bf + tn * 4);
#pragma unroll
    for (int i = 0; i < 4; ++i) {
        int m = node0 + m0 + i;
        if (m < NN) {
            int o = m * 64 + tn * 4;
            float4 lx = make_float4(acc[i][0][0] + b_l.x, acc[i][0][1] + b_l.y,
                                    acc[i][0][2] + b_l.z, acc[i][0][3] + b_l.w);
            float4 dd = make_float4(fmaxf(acc[i][1][0] + b_d.x, 0.f), fmaxf(acc[i][1][1] + b_d.y, 0.f),
                                    fmaxf(acc[i][1][2] + b_d.z, 0.f), fmaxf(acc[i][1][3] + b_d.w, 0.f));
            float4 ff = make_float4(acc[i][2][0] + b_f.x, acc[i][2][1] + b_f.y,
                                    acc[i][2][2] + b_f.z, acc[i][2][3] + b_f.w);
            *reinterpret_cast<float4*>(g_lx + o) = lx;
            *reinterpret_cast<float4*>(g_dd + o) = dd;
            *reinterpret_cast<float4*>(g_ff + o) = ff;
        }
    }
}

// ---------------- fused MLP block: h += gelu(h@W1+b1)@W2+b2 ----------------
__global__ void mlp_kernel(const float* __restrict__ W1, const float* __restrict__ b1,
                           const float* __restrict__ W2, const float* __restrict__ b2) {
    extern __shared__ float sm[];
    float* W1s = sm;                 // 4096
    float* W2s = sm + 4096;          // 4096
    float* Xs  = sm + 8192;          // 64*68
    float* Ts  = sm + 8192 + 4352;   // 64*68
    int tid = threadIdx.x;
    for (int i = tid; i < 1024; i += 256) {
        reinterpret_cast<float4*>(W1s)[i] = reinterpret_cast<const float4*>(W1)[i];
        reinterpret_cast<float4*>(W2s)[i] = reinterpret_cast<const float4*>(W2)[i];
    }
    int node0 = blockIdx.x * 64;
    load_xtile(g_x, Xs, node0, NN, tid);
    __syncthreads();

    int tm = tid & 15, tn = tid >> 4;
    int m0 = tm * 4;
    float acc[4][4];
#pragma unroll
    for (int i = 0; i < 4; ++i)
#pragma unroll
        for (int j = 0; j < 4; ++j) acc[i][j] = 0.f;

#pragma unroll 4
    for (int k = 0; k < 64; ++k) {
        float4 xv = *reinterpret_cast<const float4*>(Xs + k * 68 + m0);
        float xr[4] = {xv.x, xv.y, xv.z, xv.w};
        float4 wv = *reinterpret_cast<const float4*>(W1s + k * 64 + tn * 4);
        float wr[4] = {wv.x, wv.y, wv.z, wv.w};
#pragma unroll
        for (int i = 0; i < 4; ++i)
#pragma unroll
            for (int j = 0; j < 4; ++j) acc[i][j] = fmaf(xr[i], wr[j], acc[i][j]);
    }
    float4 bb1 = *reinterpret_cast<const float4*>(b1 + tn * 4);
    float br1[4] = {bb1.x, bb1.y, bb1.z, bb1.w};
#pragma unroll
    for (int i = 0; i < 4; ++i)
#pragma unroll
        for (int j = 0; j < 4; ++j)
            Ts[(tn * 4 + j) * 68 + m0 + i] = gelu_tanh(acc[i][j] + br1[j]);
    __syncthreads();

    float acc2[4][4];
#pragma unroll
    for (int i = 0; i < 4; ++i)
#pragma unroll
        for (int j = 0; j < 4; ++j) acc2[i][j] = 0.f;
#pragma unroll 4
    for (int k = 0; k < 64; ++k) {
        float4 tv = *reinterpret_cast<const float4*>(Ts + k * 68 + m0);
        float tr[4] = {tv.x, tv.y, tv.z, tv.w};
        float4 wv = *reinterpret_cast<const float4*>(W2s + k * 64 + tn * 4);
        float wr[4] = {wv.x, wv.y, wv.z, wv.w};
#pragma unroll
        for (int i = 0; i < 4; ++i)
#pragma unroll
            for (int j = 0; j < 4; ++j) acc2[i][j] = fmaf(tr[i], wr[j], acc2[i][j]);
    }
    float4 bb2 = *reinterpret_cast<const float4*>(b2 + tn * 4);
    float br2[4] = {bb2.x, bb2.y, bb2.z, bb2.w};
#pragma unroll
    for (int i = 0; i < 4; ++i) {
        int m = node0 + m0 + i;
        if (m < NN) {
#pragma unroll
            for (int j = 0; j < 4; ++j) {
                int n = tn * 4 + j;
                g_x[m * 64 + n] = Xs[n * 68 + m0 + i] + acc2[i][j] + br2[j];
            }
        }
    }
}

// ---------------- a,b dots (also zeroes deg) ----------------
__global__ void ab_kernel(const float* __restrict__ res_w_blk,
                          const float* __restrict__ res_b_blk) {
    int warp = (blockIdx.x * blockDim.x + threadIdx.x) >> 5;
    int lane = threadIdx.x & 31;
    if (warp >= NN) return;
    float2 xv = reinterpret_cast<const float2*>(g_x)[warp * 32 + lane];
    float wa0 = res_w_blk[2 * lane], wa1 = res_w_blk[2 * lane + 1];
    float wb0 = res_w_blk[64 + 2 * lane], wb1 = res_w_blk[64 + 2 * lane + 1];
    float sa = xv.x * wa0 + xv.y * wa1;
    float sb = xv.x * wb0 + xv.y * wb1;
#pragma unroll
    for (int off = 16; off; off >>= 1) {
        sa += __shfl_xor_sync(0xFFFFFFFFu, sa, off);
        sb += __shfl_xor_sync(0xFFFFFFFFu, sb, off);
    }
    if (lane == 0) {
        g_a[warp] = sa;
        g_b[warp] = sb + res_b_blk[0];  // fold rb into b
        g_deg[warp] = 0.f;
    }
}

// ---------------- deg = segment_sum(r, row) ----------------
__global__ void deg_kernel(const int* __restrict__ ei) {
    int e = blockIdx.x * blockDim.x + threadIdx.x;
    if (e >= EE) return;
    int r = ei[e], c = ei[EE + e];
    if (r == c) return;
    float z = __ldg(&g_a[r]) + __ldg(&g_b[c]);
    if (z > 0.f) atomicAdd(&g_deg[r], z);
}

// ---------------- dinv + pack (a, dinv) ----------------
__global__ void dinv_kernel() {
    int i = blockIdx.x * blockDim.x + threadIdx.x;
    if (i >= NN) return;
    float dg = g_deg[i];
    g_ad[i] = make_float2(g_a[i], (dg > 0.f) ? rsqrtf(dg) : 0.f);
}

// ---------------- aggregation + v/x update (warp per destination node) ----------------
__global__ void agg_kernel() {
    int warp = (blockIdx.x * blockDim.x + threadIdx.x) >> 5;
    int lane = threadIdx.x & 31;
    if (warp >= NN) return;
    int c = warp;
    int p = g_ptr[c], end = g_ptr[c + 1];
    float dc = __ldg(&g_ad[c]).y;
    float bc = __ldg(&g_b[c]);
    float acc0 = 0.f, acc1 = 0.f;

    int s_next = (p < end) ? __ldg(&g_src[p]) : 0;
    while (p < end) {
        int s = s_next;
        ++p;
        s_next = (p < end) ? __ldg(&g_src[p]) : 0;
        float2 ads = __ldg(&g_ad[s]);
        float z = ads.x + bc;
        if (s != c && z > 0.f) {
            float w = z * ads.y;
            float2 lv = __ldg(reinterpret_cast<const float2*>(g_lx) + s * 32 + lane);
            acc0 = fmaf(w, lv.x, acc0);
            acc1 = fmaf(w, lv.y, acc1);
        }
    }
    int idx = c * 32 + lane;
    float2 lxc = __ldg(reinterpret_cast<const float2*>(g_lx) + idx);
    float2 ddc = __ldg(reinterpret_cast<const float2*>(g_dd) + idx);
    float2 ffc = __ldg(reinterpret_cast<const float2*>(g_ff) + idx);
    float2 vv  = reinterpret_cast<float2*>(g_v)[idx];
    float2 xx  = reinterpret_cast<float2*>(g_x)[idx];
    vv.x -= EPSF * (lxc.x - dc * acc0 + ddc.x * vv.x - ffc.x);
    vv.y -= EPSF * (lxc.y - dc * acc1 + ddc.y * vv.y - ffc.y);
    xx.x += EPSF * vv.x;
    xx.y += EPSF * vv.y;
    reinterpret_cast<float2*>(g_v)[idx] = vv;
    reinterpret_cast<float2*>(g_x)[idx] = xx;
}

// ---------------- host launch ----------------
extern "C" void kernel_launch(void* const* d_in, const int* in_sizes, int n_in,
                              void* d_out, int out_size) {
    const float* x_in    = (const float*)d_in[0];
    const int*   ei      = (const int*)  d_in[1];
    const float* enc_w   = (const float*)d_in[2];
    const float* enc_b   = (const float*)d_in[3];
    const float* vel_w   = (const float*)d_in[4];
    const float* vel_b   = (const float*)d_in[5];
    const float* res_w   = (const float*)d_in[6];
    const float* res_b   = (const float*)d_in[7];
    const float* lin_w   = (const float*)d_in[8];
    const float* lin_b   = (const float*)d_in[9];
    const float* diss_w  = (const float*)d_in[10];
    const float* diss_b  = (const float*)d_in[11];
    const float* forc_w  = (const float*)d_in[12];
    const float* forc_b  = (const float*)d_in[13];
    const float* mlp_w1  = (const float*)d_in[14];
    const float* mlp_b1  = (const float*)d_in[15];
    const float* mlp_w2  = (const float*)d_in[16];
    const float* mlp_b2  = (const float*)d_in[17];
    const float* dec_w   = (const float*)d_in[18];
    const float* dec_b   = (const float*)d_in[19];
    float* out = (float*)d_out;

    float *px, *pv;
    cudaGetSymbolAddress((void**)&px, g_x);
    cudaGetSymbolAddress((void**)&pv, g_v);

    const int K1_SMEM  = (192 * 64 + 64 * 68) * 4;
    const int MLP_SMEM = (4096 + 4096 + 2 * 64 * 68) * 4;
    cudaFuncSetAttribute(k1_kernel,  cudaFuncAttributeMaxDynamicSharedMemorySize, K1_SMEM);
    cudaFuncSetAttribute(mlp_kernel, cudaFuncAttributeMaxDynamicSharedMemorySize, MLP_SMEM);

    const int GB = (NN + 63) / 64;          // 1563 (64-node GEMM tiles)
    const int NB = (NN + 255) / 256;        // node elementwise
    const int WB = (NN + 7) / 8;            // 8 warps (nodes) per 256-thread block
    const int EB = (EE + 255) / 256;        // edge-parallel

    // CSR-by-col build (topology fixed across all iterations)
    zero_cnt_kernel<<<NB, 256>>>();
    count_kernel<<<EB, 256>>>(ei);
    scan_kernel<<<1, 1024>>>();
    scatter_kernel<<<EB, 256>>>(ei);

    // encoder
    gemm_kernel<64><<<GB, 256>>>(x_in, enc_w, enc_b, px, NN);

    for (int blk = 0; blk < 2; ++blk) {
        gemm_kernel<64><<<GB, 256>>>(px, vel_w + blk * 4096, vel_b + blk * 64, pv, NN);
        for (int it = 0; it < 4; ++it) {
            k1_kernel<<<GB, 256, K1_SMEM>>>(lin_w  + blk * 4096, lin_b  + blk * 64,
                                            diss_w + blk * 4096, diss_b + blk * 64,
                                            forc_w + blk * 4096, forc_b + blk * 64);
            ab_kernel<<<WB, 256>>>(res_w + blk * 128, res_b + blk);
            deg_kernel<<<EB, 256>>>(ei);
            dinv_kernel<<<NB, 256>>>();
            agg_kernel<<<WB, 256>>>();
        }
        mlp_kernel<<<GB, 256, MLP_SMEM>>>(mlp_w1 + blk * 4096, mlp_b1 + blk * 64,
                                          mlp_w2 + blk * 4096, mlp_b2 + blk * 64);
    }

    // decoder
    gemm_kernel<32><<<GB, 256>>>(px, dec_w, dec_b, out, NN);
}